// round 12
// baseline (speedup 1.0000x reference)
#include <cuda_runtime.h>
#include <cuda_bf16.h>
#include <math.h>
#include <stdint.h>

// Problem constants
#define NN 20000
#define EE 160000
#define DD 768
#define HH 256
#define CC 10
#define NF 513          // 2H+1
#define EPW 1026        // 2*(2H+1)
#define TCN 256         // GEMM N (fixed)

// -------- scratch (static device arrays are allowed) --------
__device__ float g_buf_h[NN * HH];
__device__ float g_buf_s[NN];
__device__ float g_dinv[NN];
__device__ int   g_cnt_dst[NN];
__device__ int   g_cnt_src[NN];
__device__ int   g_cur_dst[NN];
__device__ int   g_cur_src[NN];
__device__ int   g_rp_dst[NN + 1];
__device__ int   g_rp_src[NN + 1];
__device__ int   g_csr_srcnode[EE];
__device__ int   g_csr_eid_dst[EE];
__device__ int   g_csr_eid_src[EE];
__device__ __nv_bfloat16 g_xhi[NN * DD];
__device__ __nv_bfloat16 g_xlo[NN * DD];
__device__ __nv_bfloat16 g_h1hi[NN * HH];
__device__ __nv_bfloat16 g_h1lo[NN * HH];
__device__ __nv_bfloat16 g_bthi[HH * DD];
__device__ __nv_bfloat16 g_btlo[HH * DD];

// ================= helpers =================
__device__ __forceinline__ uint32_t smem_u32(const void* p) {
    uint32_t a;
    asm("{ .reg .u64 t; cvta.to.shared.u64 t, %1; cvt.u32.u64 %0, t; }" : "=r"(a) : "l"(p));
    return a;
}
__device__ __forceinline__ void ldsm4(uint32_t* r, uint32_t addr) {
    asm volatile("ldmatrix.sync.aligned.m8n8.x4.shared.b16 {%0,%1,%2,%3}, [%4];"
                 : "=r"(r[0]), "=r"(r[1]), "=r"(r[2]), "=r"(r[3]) : "r"(addr));
}
__device__ __forceinline__ void mma_bf16(float* c, const uint32_t* a, const uint32_t* b) {
    asm volatile(
        "mma.sync.aligned.m16n8k16.row.col.f32.bf16.bf16.f32 "
        "{%0,%1,%2,%3}, {%4,%5,%6,%7}, {%8,%9}, {%0,%1,%2,%3};"
        : "+f"(c[0]), "+f"(c[1]), "+f"(c[2]), "+f"(c[3])
        : "r"(a[0]), "r"(a[1]), "r"(a[2]), "r"(a[3]), "r"(b[0]), "r"(b[1]));
}
__device__ __forceinline__ void cp16(uint32_t dst, const void* src, int sz) {
    asm volatile("cp.async.cg.shared.global [%0], [%1], 16, %2;"
                 :: "r"(dst), "l"(src), "r"(sz));
}
#define CP_COMMIT() asm volatile("cp.async.commit_group;" ::: "memory")
#define CP_WAIT(n)  asm volatile("cp.async.wait_group %0;" :: "n"(n) : "memory")

__device__ __forceinline__ float tanh_fast(float x) {
    float y; asm("tanh.approx.f32 %0, %1;" : "=f"(y) : "f"(x)); return y;
}
__device__ __forceinline__ void bf16_split(float v, __nv_bfloat16& hi, __nv_bfloat16& lo) {
    hi = __float2bfloat16(v);
    lo = __float2bfloat16(v - __bfloat162float(hi));
}

// ================= bf16 GEMM: BM=128, BN=256, BK=32, 512 thr, 3-stage =================
// C[M x 256] = A[M x K] * Bt[256 x K]^T   (A,Bt pre-split bf16 hi/lo, row-major)
// 16 warps: 2m x 8n, warp tile 64x32. One __syncthreads per K-chunk.
#define BKK 32
#define SPAD 40                              // bf16 elems per smem row (80B)
#define MAT_A (128 * SPAD * 2)               // 10240
#define MAT_B (256 * SPAD * 2)               // 20480
#define STAGE_BYTES (2 * MAT_A + 2 * MAT_B)  // 61440
#define NSTAGE 3
#define GEMM_SMEM (NSTAGE * STAGE_BYTES)     // 184320

__global__ void __launch_bounds__(512, 1) k_gemm_bf16(
    const __nv_bfloat16* __restrict__ Ahi, const __nv_bfloat16* __restrict__ Alo,
    const __nv_bfloat16* __restrict__ Bthi, const __nv_bfloat16* __restrict__ Btlo,
    float* __restrict__ C, int M, int K)
{
    extern __shared__ char smem[];
    const uint32_t sbase = smem_u32(smem);
    const int tid = threadIdx.x;
    const int wid = tid >> 5, lane = tid & 31;
    const int row0 = blockIdx.x * 128;
    const int wm = wid & 1, wn = wid >> 1;   // 2m x 8n

    const int a_row = (lane & 7) + ((lane >> 3) & 1) * 8;
    const int a_col = ((lane >> 4) & 1) * 8;
    const int b_row = (lane & 7) + ((lane >> 4) & 1) * 8;
    const int b_col = ((lane >> 3) & 1) * 8;

    float acc[4][4][4] = {};
    const int nchunks = K / BKK;

    auto load_stage = [&](int buf, int c) {
        const int k0 = c * BKK;
        const uint32_t sA_h = sbase + buf * STAGE_BYTES;
        const uint32_t sA_l = sA_h + MAT_A;
        const uint32_t sB_h = sA_l + MAT_A;
        const uint32_t sB_l = sB_h + MAT_B;
        {   // A: 128 rows x 4 chunks of 16B; 512 ops per mat, 1 per thread
            int r = tid >> 2, ch = tid & 3;
            int gr = row0 + r;
            int ok = (gr < M);
            size_t off = (size_t)(ok ? gr : 0) * K + k0 + ch * 8;
            uint32_t d = (uint32_t)((r * SPAD + ch * 8) * 2);
            cp16(sA_h + d, Ahi + off, ok ? 16 : 0);
            cp16(sA_l + d, Alo + off, ok ? 16 : 0);
        }
        #pragma unroll
        for (int t = tid; t < 1024; t += 512) {   // B: 256 rows x 4 chunks
            int n = t >> 2, ch = t & 3;
            size_t off = (size_t)n * K + k0 + ch * 8;
            uint32_t d = (uint32_t)((n * SPAD + ch * 8) * 2);
            cp16(sB_h + d, Bthi + off, 16);
            cp16(sB_l + d, Btlo + off, 16);
        }
    };

    auto compute_stage = [&](int buf) {
        const uint32_t sA_h = sbase + buf * STAGE_BYTES;
        const uint32_t sA_l = sA_h + MAT_A;
        const uint32_t sB_h = sA_l + MAT_A;
        const uint32_t sB_l = sB_h + MAT_B;
        #pragma unroll
        for (int ks = 0; ks < 2; ++ks) {
            const int kc = ks * 16;
            uint32_t ah[4][4], al[4][4], bh[4][2], bl[4][2];
            #pragma unroll
            for (int mf = 0; mf < 4; ++mf) {
                uint32_t off = (uint32_t)((wm * 64 + mf * 16 + a_row) * SPAD + kc + a_col) * 2;
                ldsm4(ah[mf], sA_h + off);
            }
            #pragma unroll
            for (int np = 0; np < 2; ++np) {
                uint32_t off = (uint32_t)((wn * 32 + np * 16 + b_row) * SPAD + kc + b_col) * 2;
                uint32_t t[4];
                ldsm4(t, sB_h + off);
                bh[np * 2][0] = t[0]; bh[np * 2][1] = t[1];
                bh[np * 2 + 1][0] = t[2]; bh[np * 2 + 1][1] = t[3];
            }
            #pragma unroll
            for (int mf = 0; mf < 4; ++mf)
                #pragma unroll
                for (int nf = 0; nf < 4; ++nf)
                    mma_bf16(acc[mf][nf], ah[mf], bh[nf]);
            #pragma unroll
            for (int np = 0; np < 2; ++np) {
                uint32_t off = (uint32_t)((wn * 32 + np * 16 + b_row) * SPAD + kc + b_col) * 2;
                uint32_t t[4];
                ldsm4(t, sB_l + off);
                bl[np * 2][0] = t[0]; bl[np * 2][1] = t[1];
                bl[np * 2 + 1][0] = t[2]; bl[np * 2 + 1][1] = t[3];
            }
            #pragma unroll
            for (int mf = 0; mf < 4; ++mf)
                #pragma unroll
                for (int nf = 0; nf < 4; ++nf)
                    mma_bf16(acc[mf][nf], ah[mf], bl[nf]);
            #pragma unroll
            for (int mf = 0; mf < 4; ++mf) {
                uint32_t off = (uint32_t)((wm * 64 + mf * 16 + a_row) * SPAD + kc + a_col) * 2;
                ldsm4(al[mf], sA_l + off);
            }
            #pragma unroll
            for (int mf = 0; mf < 4; ++mf)
                #pragma unroll
                for (int nf = 0; nf < 4; ++nf)
                    mma_bf16(acc[mf][nf], al[mf], bh[nf]);
        }
    };

    // prologue: stages 0, 1 in flight
    load_stage(0, 0);
    CP_COMMIT();
    load_stage(1 % NSTAGE, 1);
    CP_COMMIT();

    for (int c = 0; c < nchunks; ++c) {
        if (c + 1 < nchunks) { CP_WAIT(1); } else { CP_WAIT(0); }
        __syncthreads();    // stage c visible to all; compute(c-1) done by all
        if (c + 2 < nchunks) {
            load_stage((c + 2) % NSTAGE, c + 2);
            CP_COMMIT();
        }
        compute_stage(c % NSTAGE);
    }

    const int gq = lane >> 2, rq = lane & 3;
    #pragma unroll
    for (int mf = 0; mf < 4; ++mf) {
        int gr0 = row0 + wm * 64 + mf * 16 + gq;
        int gr1 = gr0 + 8;
        #pragma unroll
        for (int nf = 0; nf < 4; ++nf) {
            int gc = wn * 32 + nf * 8 + rq * 2;
            if (gr0 < M) {
                C[(size_t)gr0 * TCN + gc]     = acc[mf][nf][0];
                C[(size_t)gr0 * TCN + gc + 1] = acc[mf][nf][1];
            }
            if (gr1 < M) {
                C[(size_t)gr1 * TCN + gc]     = acc[mf][nf][2];
                C[(size_t)gr1 * TCN + gc + 1] = acc[mf][nf][3];
            }
        }
    }
}

// ================= conversion kernels =================
__global__ void k_cvt_split(const float* __restrict__ in,
                            __nv_bfloat16* __restrict__ hi, __nv_bfloat16* __restrict__ lo,
                            int n4) {
    int i = blockIdx.x * blockDim.x + threadIdx.x;
    if (i >= n4) return;
    float4 v = reinterpret_cast<const float4*>(in)[i];
    __nv_bfloat16 h0, h1, h2, h3, l0, l1, l2, l3;
    bf16_split(v.x, h0, l0); bf16_split(v.y, h1, l1);
    bf16_split(v.z, h2, l2); bf16_split(v.w, h3, l3);
    reinterpret_cast<__nv_bfloat162*>(hi)[i * 2]     = __nv_bfloat162(h0, h1);
    reinterpret_cast<__nv_bfloat162*>(hi)[i * 2 + 1] = __nv_bfloat162(h2, h3);
    reinterpret_cast<__nv_bfloat162*>(lo)[i * 2]     = __nv_bfloat162(l0, l1);
    reinterpret_cast<__nv_bfloat162*>(lo)[i * 2 + 1] = __nv_bfloat162(l2, l3);
}

__global__ void k_cvt_w(const float* __restrict__ W,
                        __nv_bfloat16* __restrict__ bthi, __nv_bfloat16* __restrict__ btlo,
                        int K) {
    __shared__ float t[32][33];
    int kb = blockIdx.x * 32, nb = blockIdx.y * 32;
    int tx = threadIdx.x, ty = threadIdx.y;   // 32 x 8
    #pragma unroll
    for (int j = ty; j < 32; j += 8)
        t[j][tx] = W[(size_t)(kb + j) * TCN + nb + tx];
    __syncthreads();
    #pragma unroll
    for (int j = ty; j < 32; j += 8) {
        float v = t[tx][j];
        __nv_bfloat16 h, l;
        bf16_split(v, h, l);
        bthi[(size_t)(nb + j) * K + kb + tx] = h;
        btlo[(size_t)(nb + j) * K + kb + tx] = l;
    }
}

// ================= CSR build =================
__global__ void k_zero4(int* a, int* b, int* c, int* d, int n) {
    int i = blockIdx.x * blockDim.x + threadIdx.x;
    if (i < n) { a[i] = 0; b[i] = 0; c[i] = 0; d[i] = 0; }
}

__global__ void k_count2(const int* __restrict__ src, const int* __restrict__ dst,
                         int* cnt_src, int* cnt_dst, int e) {
    int i = blockIdx.x * blockDim.x + threadIdx.x;
    if (i < e) {
        atomicAdd(&cnt_dst[dst[i]], 1);
        atomicAdd(&cnt_src[src[i]], 1);
    }
}

__global__ void k_scan(const int* __restrict__ cnt, int* rowptr, int n) {
    __shared__ int wsum[32];
    __shared__ int s_carry;
    int lane = threadIdx.x & 31, wid = threadIdx.x >> 5;
    if (threadIdx.x == 0) { rowptr[0] = 0; s_carry = 0; }
    __syncthreads();
    for (int base = 0; base < n; base += 1024) {
        int i = base + threadIdx.x;
        int x = (i < n) ? cnt[i] : 0;
        #pragma unroll
        for (int off = 1; off < 32; off <<= 1) {
            int t = __shfl_up_sync(0xffffffffu, x, off);
            if (lane >= off) x += t;
        }
        if (lane == 31) wsum[wid] = x;
        __syncthreads();
        if (wid == 0) {
            int w = wsum[lane];
            #pragma unroll
            for (int off = 1; off < 32; off <<= 1) {
                int t = __shfl_up_sync(0xffffffffu, w, off);
                if (lane >= off) w += t;
            }
            wsum[lane] = w;
        }
        __syncthreads();
        int carry_now = s_carry;
        int excl_w = (wid > 0) ? wsum[wid - 1] : 0;
        if (i < n) rowptr[i + 1] = x + excl_w + carry_now;
        __syncthreads();
        if (threadIdx.x == 0) s_carry = carry_now + wsum[31];
        __syncthreads();
    }
}

__global__ void k_dinv(const int* __restrict__ cnt, float* dinv, int n) {
    int i = blockIdx.x * blockDim.x + threadIdx.x;
    if (i < n) dinv[i] = rsqrtf((float)(cnt[i] + 1));
}

__global__ void k_fill(const int* __restrict__ src, const int* __restrict__ dst,
                       const int* __restrict__ rp_dst, const int* __restrict__ rp_src,
                       int* cur_dst, int* cur_src,
                       int* csr_srcnode, int* csr_eid_dst, int* csr_eid_src, int e) {
    int i = blockIdx.x * blockDim.x + threadIdx.x;
    if (i < e) {
        int s = src[i], d = dst[i];
        int pd = rp_dst[d] + atomicAdd(&cur_dst[d], 1);
        csr_srcnode[pd] = s;
        csr_eid_dst[pd] = i;
        int ps = rp_src[s] + atomicAdd(&cur_src[s], 1);
        csr_eid_src[ps] = i;
    }
}

// ================= aggregation (MLP=4 unrolled) =================
__global__ void k_agg1(const float* __restrict__ h,
                       float* __restrict__ nf,
                       const int* __restrict__ rowptr, const int* __restrict__ csrc,
                       const float* __restrict__ dinv, const float* __restrict__ bias,
                       __nv_bfloat16* __restrict__ h1hi, __nv_bfloat16* __restrict__ h1lo) {
    int v = blockIdx.x;
    int col = threadIdx.x;
    float dv = dinv[v];
    int e0 = rowptr[v], e1 = rowptr[v + 1];
    float a0 = h[(size_t)v * HH + col] * dv, a1 = 0.f, a2 = 0.f, a3 = 0.f;
    int e = e0;
    for (; e + 4 <= e1; e += 4) {
        int s0 = csrc[e], s1 = csrc[e + 1], s2 = csrc[e + 2], s3 = csrc[e + 3];
        float w0 = dinv[s0], w1 = dinv[s1], w2 = dinv[s2], w3 = dinv[s3];
        float v0 = h[(size_t)s0 * HH + col];
        float v1 = h[(size_t)s1 * HH + col];
        float v2 = h[(size_t)s2 * HH + col];
        float v3 = h[(size_t)s3 * HH + col];
        a0 = fmaf(v0, w0, a0); a1 = fmaf(v1, w1, a1);
        a2 = fmaf(v2, w2, a2); a3 = fmaf(v3, w3, a3);
    }
    for (; e < e1; ++e) {
        int s = csrc[e];
        a0 = fmaf(h[(size_t)s * HH + col], dinv[s], a0);
    }
    float acc = (a0 + a1) + (a2 + a3);
    float r = tanh_fast(acc * dv + bias[col]);
    nf[(size_t)v * NF + col] = r;
    __nv_bfloat16 hi, lo;
    bf16_split(r, hi, lo);
    h1hi[(size_t)v * HH + col] = hi;
    h1lo[(size_t)v * HH + col] = lo;
}

__global__ void k_agg2(const float* __restrict__ h,
                       float* __restrict__ nf,
                       const int* __restrict__ rowptr, const int* __restrict__ csrc,
                       const float* __restrict__ dinv, const float* __restrict__ bias,
                       const float* __restrict__ W2, float* __restrict__ sv) {
    __shared__ float red[8];
    int v = blockIdx.x;
    int col = threadIdx.x;
    int lane = col & 31, wrp = col >> 5;
    float dv = dinv[v];
    int e0 = rowptr[v], e1 = rowptr[v + 1];
    float a0 = h[(size_t)v * HH + col] * dv, a1 = 0.f, a2 = 0.f, a3 = 0.f;
    int e = e0;
    for (; e + 4 <= e1; e += 4) {
        int s0 = csrc[e], s1 = csrc[e + 1], s2 = csrc[e + 2], s3 = csrc[e + 3];
        float w0 = dinv[s0], w1 = dinv[s1], w2 = dinv[s2], w3 = dinv[s3];
        float v0 = h[(size_t)s0 * HH + col];
        float v1 = h[(size_t)s1 * HH + col];
        float v2 = h[(size_t)s2 * HH + col];
        float v3 = h[(size_t)s3 * HH + col];
        a0 = fmaf(v0, w0, a0); a1 = fmaf(v1, w1, a1);
        a2 = fmaf(v2, w2, a2); a3 = fmaf(v3, w3, a3);
    }
    for (; e < e1; ++e) {
        int s = csrc[e];
        a0 = fmaf(h[(size_t)s * HH + col], dinv[s], a0);
    }
    float acc = (a0 + a1) + (a2 + a3);
    float r = tanh_fast(acc * dv + bias[col]);
    nf[(size_t)v * NF + HH + col] = r;
    float p = r * W2[col];
    #pragma unroll
    for (int off = 16; off; off >>= 1) p += __shfl_xor_sync(0xffffffffu, p, off);
    if (lane == 0) red[wrp] = p;
    __syncthreads();
    if (col == 0) {
        float t = 0.f;
        #pragma unroll
        for (int w = 0; w < 8; ++w) t += red[w];
        sv[v] = t;
    }
}

__global__ void k_agg_scalar(const float* __restrict__ s, float* __restrict__ nf,
                             const int* __restrict__ rowptr, const int* __restrict__ csrc,
                             const float* __restrict__ dinv, const float* __restrict__ b2, int n) {
    int v = blockIdx.x * blockDim.x + threadIdx.x;
    if (v >= n) return;
    float dv = dinv[v];
    int e0 = rowptr[v], e1 = rowptr[v + 1];
    float a0 = s[v] * dv, a1 = 0.f, a2 = 0.f, a3 = 0.f;
    int e = e0;
    for (; e + 4 <= e1; e += 4) {
        int s0 = csrc[e], s1 = csrc[e + 1], s2 = csrc[e + 2], s3 = csrc[e + 3];
        a0 = fmaf(s[s0], dinv[s0], a0); a1 = fmaf(s[s1], dinv[s1], a1);
        a2 = fmaf(s[s2], dinv[s2], a2); a3 = fmaf(s[s3], dinv[s3], a3);
    }
    for (; e < e1; ++e) {
        int sn = csrc[e];
        a0 = fmaf(s[sn], dinv[sn], a0);
    }
    float acc = (a0 + a1) + (a2 + a3);
    nf[(size_t)v * NF + (NF - 1)] = tanh_fast(acc * dv + b2[0]);
}

__global__ void k_logits(const float* __restrict__ nf, const float* __restrict__ Wc,
                         const float* __restrict__ bc, float* __restrict__ out, int n) {
    int gwarp = (blockIdx.x * blockDim.x + threadIdx.x) >> 5;
    int lane = threadIdx.x & 31;
    if (gwarp >= n) return;
    const float* row = nf + (size_t)gwarp * NF;
    float acc[CC] = {};
    for (int j = lane; j < NF; j += 32) {
        float v = row[j];
        const float* w = Wc + (size_t)j * CC;
        #pragma unroll
        for (int c = 0; c < CC; ++c) acc[c] = fmaf(v, w[c], acc[c]);
    }
    #pragma unroll
    for (int c = 0; c < CC; ++c)
        #pragma unroll
        for (int off = 16; off; off >>= 1) acc[c] += __shfl_xor_sync(0xffffffffu, acc[c], off);
    if (lane == 0) {
        #pragma unroll
        for (int c = 0; c < CC; ++c) out[(size_t)gwarp * CC + c] = acc[c] + bc[c];
    }
}

__global__ void k_edge_scatter(const float* __restrict__ nf,
                               const int* __restrict__ rp_src, const int* __restrict__ eid_src,
                               const int* __restrict__ rp_dst, const int* __restrict__ eid_dst,
                               float* __restrict__ ep) {
    __shared__ float row[NF];
    int v = blockIdx.x;
    for (int j = threadIdx.x; j < NF; j += blockDim.x)
        row[j] = nf[(size_t)v * NF + j];
    __syncthreads();
    int s0 = rp_src[v], s1 = rp_src[v + 1];
    for (int e = s0; e < s1; ++e) {
        float* o = ep + (size_t)eid_src[e] * EPW;
        for (int j = threadIdx.x; j < NF; j += blockDim.x)
            __stcs(o + j, row[j]);
    }
    int d0 = rp_dst[v], d1 = rp_dst[v + 1];
    for (int e = d0; e < d1; ++e) {
        float* o = ep + (size_t)eid_dst[e] * EPW + NF;
        for (int j = threadIdx.x; j < NF; j += blockDim.x)
            __stcs(o + j, row[j]);
    }
}

// ================= launch =================
extern "C" void kernel_launch(void* const* d_in, const int* in_sizes, int n_in,
                              void* d_out, int out_size) {
    const float* x    = (const float*)d_in[0];
    const int*   ei   = (const int*)d_in[1];
    const float* W0   = (const float*)d_in[2];
    const float* b0   = (const float*)d_in[3];
    const float* W1   = (const float*)d_in[4];
    const float* b1   = (const float*)d_in[5];
    const float* W2   = (const float*)d_in[6];
    const float* b2   = (const float*)d_in[7];
    const float* Wc   = (const float*)d_in[8];
    const float* bc   = (const float*)d_in[9];

    const int n = in_sizes[0] / DD;
    const int e = in_sizes[1] / 2;
    const int* src = ei;
    const int* dst = ei + e;

    float* out = (float*)d_out;
    float* logits = out;
    float* nf     = out + (size_t)n * CC;
    float* ep     = nf + (size_t)n * NF;

    float *buf_h, *buf_s, *dinv;
    int *cnt_d, *cnt_s, *cur_d, *cur_s, *rp_d, *rp_s, *csrn, *eid_d, *eid_s;
    __nv_bfloat16 *xhi, *xlo, *h1hi, *h1lo, *bthi, *btlo;
    cudaGetSymbolAddress((void**)&buf_h, g_buf_h);
    cudaGetSymbolAddress((void**)&buf_s, g_buf_s);
    cudaGetSymbolAddress((void**)&dinv, g_dinv);
    cudaGetSymbolAddress((void**)&cnt_d, g_cnt_dst);
    cudaGetSymbolAddress((void**)&cnt_s, g_cnt_src);
    cudaGetSymbolAddress((void**)&cur_d, g_cur_dst);
    cudaGetSymbolAddress((void**)&cur_s, g_cur_src);
    cudaGetSymbolAddress((void**)&rp_d, g_rp_dst);
    cudaGetSymbolAddress((void**)&rp_s, g_rp_src);
    cudaGetSymbolAddress((void**)&csrn, g_csr_srcnode);
    cudaGetSymbolAddress((void**)&eid_d, g_csr_eid_dst);
    cudaGetSymbolAddress((void**)&eid_s, g_csr_eid_src);
    cudaGetSymbolAddress((void**)&xhi, g_xhi);
    cudaGetSymbolAddress((void**)&xlo, g_xlo);
    cudaGetSymbolAddress((void**)&h1hi, g_h1hi);
    cudaGetSymbolAddress((void**)&h1lo, g_h1lo);
    cudaGetSymbolAddress((void**)&bthi, g_bthi);
    cudaGetSymbolAddress((void**)&btlo, g_btlo);

    cudaFuncSetAttribute(k_gemm_bf16, cudaFuncAttributeMaxDynamicSharedMemorySize, GEMM_SMEM);

    const int TB = 256;
    dim3 gg((n + 127) / 128);
    dim3 wb0(DD / 32, TCN / 32), wb1(HH / 32, TCN / 32);
    dim3 wt(32, 8);

    // -- launches ordered so GEMM1 is launch index 3 (ncu's capture slot) --
    k_zero4<<<(n + TB - 1) / TB, TB>>>(cnt_d, cnt_s, cur_d, cur_s, n);             // 0
    k_cvt_w<<<wb0, wt>>>(W0, bthi, btlo, DD);                                      // 1
    k_cvt_split<<<(n * DD / 4 + TB - 1) / TB, TB>>>(x, xhi, xlo, n * DD / 4);      // 2
    k_gemm_bf16<<<gg, 512, GEMM_SMEM>>>(xhi, xlo, bthi, btlo, buf_h, n, DD);       // 3
    k_count2<<<(e + TB - 1) / TB, TB>>>(src, dst, cnt_s, cnt_d, e);                // 4
    k_scan<<<1, 1024>>>(cnt_d, rp_d, n);                                           // 5
    k_scan<<<1, 1024>>>(cnt_s, rp_s, n);                                           // 6
    k_dinv<<<(n + TB - 1) / TB, TB>>>(cnt_d, dinv, n);                             // 7
    k_fill<<<(e + TB - 1) / TB, TB>>>(src, dst, rp_d, rp_s, cur_d, cur_s,
                                      csrn, eid_d, eid_s, e);                      // 8
    k_agg1<<<n, HH>>>(buf_h, nf, rp_d, csrn, dinv, b0, h1hi, h1lo);                // 9
    k_cvt_w<<<wb1, wt>>>(W1, bthi, btlo, HH);                                      // 10
    k_gemm_bf16<<<gg, 512, GEMM_SMEM>>>(h1hi, h1lo, bthi, btlo, buf_h, n, HH);     // 11
    k_agg2<<<n, HH>>>(buf_h, nf, rp_d, csrn, dinv, b1, W2, buf_s);                 // 12
    k_agg_scalar<<<(n + TB - 1) / TB, TB>>>(buf_s, nf, rp_d, csrn, dinv, b2, n);   // 13
    k_logits<<<(n * 32 + TB - 1) / TB, TB>>>(nf, Wc, bc, logits, n);               // 14
    k_edge_scatter<<<n, 256>>>(nf, rp_s, eid_s, rp_d, eid_d, ep);                  // 15
}

// round 14
// speedup vs baseline: 1.1567x; 1.1567x over previous
#include <cuda_runtime.h>
#include <cuda_bf16.h>
#include <math.h>
#include <stdint.h>

// Problem constants
#define NN 20000
#define EE 160000
#define DD 768
#define HH 256
#define CC 10
#define NF 513          // 2H+1
#define EPW 1026        // 2*(2H+1)
#define TCN 256         // GEMM N (fixed)

// -------- scratch (static device arrays are allowed) --------
__device__ float g_buf_h[NN * HH];
__device__ float g_buf_s[NN];
__device__ float g_dinv[NN];
__device__ int   g_cnt_dst[NN];
__device__ int   g_cnt_src[NN];
__device__ int   g_cur_dst[NN];
__device__ int   g_cur_src[NN];
__device__ int   g_rp_dst[NN + 1];
__device__ int   g_rp_src[NN + 1];
__device__ int   g_csr_srcnode[EE];
__device__ int   g_csr_eid_dst[EE];
__device__ int   g_csr_eid_src[EE];
__device__ __nv_bfloat16 g_xhi[NN * DD];
__device__ __nv_bfloat16 g_xlo[NN * DD];
__device__ __nv_bfloat16 g_h1hi[NN * HH];
__device__ __nv_bfloat16 g_h1lo[NN * HH];
__device__ __nv_bfloat16 g_bthi[HH * DD];
__device__ __nv_bfloat16 g_btlo[HH * DD];

// ================= helpers =================
__device__ __forceinline__ uint32_t smem_u32(const void* p) {
    uint32_t a;
    asm("{ .reg .u64 t; cvta.to.shared.u64 t, %1; cvt.u32.u64 %0, t; }" : "=r"(a) : "l"(p));
    return a;
}
__device__ __forceinline__ void ldsm4(uint32_t* r, uint32_t addr) {
    asm volatile("ldmatrix.sync.aligned.m8n8.x4.shared.b16 {%0,%1,%2,%3}, [%4];"
                 : "=r"(r[0]), "=r"(r[1]), "=r"(r[2]), "=r"(r[3]) : "r"(addr));
}
__device__ __forceinline__ void mma_bf16(float* c, const uint32_t* a, const uint32_t* b) {
    asm volatile(
        "mma.sync.aligned.m16n8k16.row.col.f32.bf16.bf16.f32 "
        "{%0,%1,%2,%3}, {%4,%5,%6,%7}, {%8,%9}, {%0,%1,%2,%3};"
        : "+f"(c[0]), "+f"(c[1]), "+f"(c[2]), "+f"(c[3])
        : "r"(a[0]), "r"(a[1]), "r"(a[2]), "r"(a[3]), "r"(b[0]), "r"(b[1]));
}
__device__ __forceinline__ void cp16(uint32_t dst, const void* src, int sz) {
    asm volatile("cp.async.cg.shared.global [%0], [%1], 16, %2;"
                 :: "r"(dst), "l"(src), "r"(sz));
}
#define CP_COMMIT() asm volatile("cp.async.commit_group;" ::: "memory")
#define CP_WAIT(n)  asm volatile("cp.async.wait_group %0;" :: "n"(n) : "memory")

__device__ __forceinline__ float tanh_fast(float x) {
    float y; asm("tanh.approx.f32 %0, %1;" : "=f"(y) : "f"(x)); return y;
}
__device__ __forceinline__ void bf16_split(float v, __nv_bfloat16& hi, __nv_bfloat16& lo) {
    hi = __float2bfloat16(v);
    lo = __float2bfloat16(v - __bfloat162float(hi));
}

// ================= bf16 GEMM: BM=128, BN=128, BK=32, 256 thr, 2-stage, 1 barrier/chunk ====
// C[M x 256] = A[M x K] * Bt[256 x K]^T   (A,Bt pre-split bf16 hi/lo, row-major)
// 8 warps: 2m x 4n, warp tile 64x32. 2 blocks/SM.
#define BKK 32
#define SPAD 40                              // bf16 elems per smem row (80B)
#define MAT_BYTES (128 * SPAD * 2)           // 10240
#define STAGE_BYTES (4 * MAT_BYTES)          // Ah, Al, Bh, Bl = 40960
#define GEMM_SMEM (2 * STAGE_BYTES)          // 81920

__global__ void __launch_bounds__(256, 2) k_gemm_bf16(
    const __nv_bfloat16* __restrict__ Ahi, const __nv_bfloat16* __restrict__ Alo,
    const __nv_bfloat16* __restrict__ Bthi, const __nv_bfloat16* __restrict__ Btlo,
    float* __restrict__ C, int M, int K)
{
    extern __shared__ char smem[];
    const uint32_t sbase = smem_u32(smem);
    const int tid = threadIdx.x;
    const int wid = tid >> 5, lane = tid & 31;
    const int row0 = blockIdx.x * 128;
    const int col0 = blockIdx.y * 128;
    const int wm = wid & 1, wn = wid >> 1;

    const int a_row = (lane & 7) + ((lane >> 3) & 1) * 8;
    const int a_col = ((lane >> 4) & 1) * 8;
    const int b_row = (lane & 7) + ((lane >> 4) & 1) * 8;
    const int b_col = ((lane >> 3) & 1) * 8;

    float acc[4][4][4] = {};
    const int nchunks = K / BKK;

    auto load_stage = [&](int buf, int c) {
        const int k0 = c * BKK;
        const uint32_t sA_h = sbase + buf * STAGE_BYTES;
        const uint32_t sA_l = sA_h + MAT_BYTES;
        const uint32_t sB_h = sA_l + MAT_BYTES;
        const uint32_t sB_l = sB_h + MAT_BYTES;
        #pragma unroll
        for (int t = tid; t < 512; t += 256) {          // A: 128 rows x 4 chunks
            int r = t >> 2, ch = t & 3;
            int gr = row0 + r;
            int ok = (gr < M);
            size_t off = (size_t)(ok ? gr : 0) * K + k0 + ch * 8;
            uint32_t d = (uint32_t)((r * SPAD + ch * 8) * 2);
            cp16(sA_h + d, Ahi + off, ok ? 16 : 0);
            cp16(sA_l + d, Alo + off, ok ? 16 : 0);
        }
        #pragma unroll
        for (int t = tid; t < 512; t += 256) {          // B: 128 n-rows x 4 chunks
            int n = t >> 2, ch = t & 3;
            size_t off = (size_t)(col0 + n) * K + k0 + ch * 8;
            uint32_t d = (uint32_t)((n * SPAD + ch * 8) * 2);
            cp16(sB_h + d, Bthi + off, 16);
            cp16(sB_l + d, Btlo + off, 16);
        }
    };

    auto compute_stage = [&](int buf) {
        const uint32_t sA_h = sbase + buf * STAGE_BYTES;
        const uint32_t sA_l = sA_h + MAT_BYTES;
        const uint32_t sB_h = sA_l + MAT_BYTES;
        const uint32_t sB_l = sB_h + MAT_BYTES;
        #pragma unroll
        for (int ks = 0; ks < 2; ++ks) {
            const int kc = ks * 16;
            uint32_t ah[4][4], al[4][4], bh[4][2], bl[4][2];
            #pragma unroll
            for (int mf = 0; mf < 4; ++mf) {
                uint32_t off = (uint32_t)((wm * 64 + mf * 16 + a_row) * SPAD + kc + a_col) * 2;
                ldsm4(ah[mf], sA_h + off);
            }
            #pragma unroll
            for (int np = 0; np < 2; ++np) {
                uint32_t off = (uint32_t)((wn * 32 + np * 16 + b_row) * SPAD + kc + b_col) * 2;
                uint32_t t[4];
                ldsm4(t, sB_h + off);
                bh[np * 2][0] = t[0]; bh[np * 2][1] = t[1];
                bh[np * 2 + 1][0] = t[2]; bh[np * 2 + 1][1] = t[3];
            }
            #pragma unroll
            for (int mf = 0; mf < 4; ++mf)
                #pragma unroll
                for (int nf = 0; nf < 4; ++nf)
                    mma_bf16(acc[mf][nf], ah[mf], bh[nf]);
            #pragma unroll
            for (int np = 0; np < 2; ++np) {
                uint32_t off = (uint32_t)((wn * 32 + np * 16 + b_row) * SPAD + kc + b_col) * 2;
                uint32_t t[4];
                ldsm4(t, sB_l + off);
                bl[np * 2][0] = t[0]; bl[np * 2][1] = t[1];
                bl[np * 2 + 1][0] = t[2]; bl[np * 2 + 1][1] = t[3];
            }
            #pragma unroll
            for (int mf = 0; mf < 4; ++mf)
                #pragma unroll
                for (int nf = 0; nf < 4; ++nf)
                    mma_bf16(acc[mf][nf], ah[mf], bl[nf]);
            #pragma unroll
            for (int mf = 0; mf < 4; ++mf) {
                uint32_t off = (uint32_t)((wm * 64 + mf * 16 + a_row) * SPAD + kc + a_col) * 2;
                ldsm4(al[mf], sA_l + off);
            }
            #pragma unroll
            for (int mf = 0; mf < 4; ++mf)
                #pragma unroll
                for (int nf = 0; nf < 4; ++nf)
                    mma_bf16(acc[mf][nf], al[mf], bh[nf]);
        }
    };

    // 2-stage pipeline, ONE barrier per chunk:
    //   wait(load c) -> sync (publishes c; WAR-safe since compute(c-1) preceded) ->
    //   issue load(c+1) -> compute(c)
    load_stage(0, 0);
    CP_COMMIT();
    for (int c = 0; c < nchunks; ++c) {
        CP_WAIT(0);
        __syncthreads();
        if (c + 1 < nchunks) {
            load_stage((c + 1) & 1, c + 1);
            CP_COMMIT();
        }
        compute_stage(c & 1);
    }

    const int gq = lane >> 2, rq = lane & 3;
    #pragma unroll
    for (int mf = 0; mf < 4; ++mf) {
        int gr0 = row0 + wm * 64 + mf * 16 + gq;
        int gr1 = gr0 + 8;
        #pragma unroll
        for (int nf = 0; nf < 4; ++nf) {
            int gc = col0 + wn * 32 + nf * 8 + rq * 2;
            if (gr0 < M) {
                C[(size_t)gr0 * TCN + gc]     = acc[mf][nf][0];
                C[(size_t)gr0 * TCN + gc + 1] = acc[mf][nf][1];
            }
            if (gr1 < M) {
                C[(size_t)gr1 * TCN + gc]     = acc[mf][nf][2];
                C[(size_t)gr1 * TCN + gc + 1] = acc[mf][nf][3];
            }
        }
    }
}

// ================= fused prep: zero counters + cvt W0 + cvt x =================
// grid layout: [0, ZB) zero | [ZB, ZB+WB) cvt_w W0 | [ZB+WB, ...) cvt_split x
#define ZB 79                        // ceil(20000/256)
#define WB_K (DD / 32)               // 24
#define WB_N (TCN / 32)              // 8
#define WB (WB_K * WB_N)             // 192
#define XB (NN * DD / 4 / 256)       // 15000

__global__ void k_prep(const float* __restrict__ x, const float* __restrict__ W0,
                       int* cnt_d, int* cnt_s, int* cur_d, int* cur_s,
                       __nv_bfloat16* __restrict__ xhi, __nv_bfloat16* __restrict__ xlo,
                       __nv_bfloat16* __restrict__ bthi, __nv_bfloat16* __restrict__ btlo) {
    int b = blockIdx.x;
    if (b < ZB) {
        int i = b * 256 + threadIdx.x;
        if (i < NN) { cnt_d[i] = 0; cnt_s[i] = 0; cur_d[i] = 0; cur_s[i] = 0; }
        return;
    }
    b -= ZB;
    if (b < WB) {
        __shared__ float t[32][33];
        int kb = (b % WB_K) * 32, nb = (b / WB_K) * 32;
        int tx = threadIdx.x & 31, ty = threadIdx.x >> 5;
        #pragma unroll
        for (int j = ty; j < 32; j += 8)
            t[j][tx] = W0[(size_t)(kb + j) * TCN + nb + tx];
        __syncthreads();
        #pragma unroll
        for (int j = ty; j < 32; j += 8) {
            __nv_bfloat16 h, l;
            bf16_split(t[tx][j], h, l);
            bthi[(size_t)(nb + j) * DD + kb + tx] = h;
            btlo[(size_t)(nb + j) * DD + kb + tx] = l;
        }
        return;
    }
    b -= WB;
    int i = b * 256 + threadIdx.x;
    float4 v = reinterpret_cast<const float4*>(x)[i];
    __nv_bfloat16 h0, h1, h2, h3, l0, l1, l2, l3;
    bf16_split(v.x, h0, l0); bf16_split(v.y, h1, l1);
    bf16_split(v.z, h2, l2); bf16_split(v.w, h3, l3);
    reinterpret_cast<__nv_bfloat162*>(xhi)[i * 2]     = __nv_bfloat162(h0, h1);
    reinterpret_cast<__nv_bfloat162*>(xhi)[i * 2 + 1] = __nv_bfloat162(h2, h3);
    reinterpret_cast<__nv_bfloat162*>(xlo)[i * 2]     = __nv_bfloat162(l0, l1);
    reinterpret_cast<__nv_bfloat162*>(xlo)[i * 2 + 1] = __nv_bfloat162(l2, l3);
}

__global__ void k_cvt_w(const float* __restrict__ W,
                        __nv_bfloat16* __restrict__ bthi, __nv_bfloat16* __restrict__ btlo,
                        int K) {
    __shared__ float t[32][33];
    int kb = blockIdx.x * 32, nb = blockIdx.y * 32;
    int tx = threadIdx.x, ty = threadIdx.y;
    #pragma unroll
    for (int j = ty; j < 32; j += 8)
        t[j][tx] = W[(size_t)(kb + j) * TCN + nb + tx];
    __syncthreads();
    #pragma unroll
    for (int j = ty; j < 32; j += 8) {
        __nv_bfloat16 h, l;
        bf16_split(t[tx][j], h, l);
        bthi[(size_t)(nb + j) * K + kb + tx] = h;
        btlo[(size_t)(nb + j) * K + kb + tx] = l;
    }
}

// ================= CSR build =================
__global__ void k_count2(const int* __restrict__ src, const int* __restrict__ dst,
                         int* cnt_src, int* cnt_dst, int e) {
    int i = blockIdx.x * blockDim.x + threadIdx.x;
    if (i < e) {
        atomicAdd(&cnt_dst[dst[i]], 1);
        atomicAdd(&cnt_src[src[i]], 1);
    }
}

// 2 blocks: block 0 scans cnt_d -> rp_d (+ dinv), block 1 scans cnt_s -> rp_s
__global__ void k_scan2(const int* __restrict__ cnt_d, const int* __restrict__ cnt_s,
                        int* rp_d, int* rp_s, float* dinv, int n) {
    const int* cnt = (blockIdx.x == 0) ? cnt_d : cnt_s;
    int* rowptr    = (blockIdx.x == 0) ? rp_d : rp_s;
    __shared__ int wsum[32];
    __shared__ int s_carry;
    int lane = threadIdx.x & 31, wid = threadIdx.x >> 5;
    if (threadIdx.x == 0) { rowptr[0] = 0; s_carry = 0; }
    __syncthreads();
    for (int base = 0; base < n; base += 1024) {
        int i = base + threadIdx.x;
        int x = (i < n) ? cnt[i] : 0;
        #pragma unroll
        for (int off = 1; off < 32; off <<= 1) {
            int t = __shfl_up_sync(0xffffffffu, x, off);
            if (lane >= off) x += t;
        }
        if (lane == 31) wsum[wid] = x;
        __syncthreads();
        if (wid == 0) {
            int w = wsum[lane];
            #pragma unroll
            for (int off = 1; off < 32; off <<= 1) {
                int t = __shfl_up_sync(0xffffffffu, w, off);
                if (lane >= off) w += t;
            }
            wsum[lane] = w;
        }
        __syncthreads();
        int carry_now = s_carry;
        int excl_w = (wid > 0) ? wsum[wid - 1] : 0;
        if (i < n) rowptr[i + 1] = x + excl_w + carry_now;
        __syncthreads();
        if (threadIdx.x == 0) s_carry = carry_now + wsum[31];
        __syncthreads();
    }
    if (blockIdx.x == 0) {
        for (int i = threadIdx.x; i < n; i += 1024)
            dinv[i] = rsqrtf((float)(cnt_d[i] + 1));
    }
}

__global__ void k_fill(const int* __restrict__ src, const int* __restrict__ dst,
                       const int* __restrict__ rp_dst, const int* __restrict__ rp_src,
                       int* cur_dst, int* cur_src,
                       int* csr_srcnode, int* csr_eid_dst, int* csr_eid_src, int e) {
    int i = blockIdx.x * blockDim.x + threadIdx.x;
    if (i < e) {
        int s = src[i], d = dst[i];
        int pd = rp_dst[d] + atomicAdd(&cur_dst[d], 1);
        csr_srcnode[pd] = s;
        csr_eid_dst[pd] = i;
        int ps = rp_src[s] + atomicAdd(&cur_src[s], 1);
        csr_eid_src[ps] = i;
    }
}

// ================= aggregation (MLP=4) =================
__global__ void k_agg1(const float* __restrict__ h,
                       float* __restrict__ nf,
                       const int* __restrict__ rowptr, const int* __restrict__ csrc,
                       const float* __restrict__ dinv, const float* __restrict__ bias,
                       __nv_bfloat16* __restrict__ h1hi, __nv_bfloat16* __restrict__ h1lo) {
    int v = blockIdx.x;
    int col = threadIdx.x;
    float dv = dinv[v];
    int e0 = rowptr[v], e1 = rowptr[v + 1];
    float a0 = h[(size_t)v * HH + col] * dv, a1 = 0.f, a2 = 0.f, a3 = 0.f;
    int e = e0;
    for (; e + 4 <= e1; e += 4) {
        int s0 = csrc[e], s1 = csrc[e + 1], s2 = csrc[e + 2], s3 = csrc[e + 3];
        float w0 = dinv[s0], w1 = dinv[s1], w2 = dinv[s2], w3 = dinv[s3];
        float v0 = h[(size_t)s0 * HH + col];
        float v1 = h[(size_t)s1 * HH + col];
        float v2 = h[(size_t)s2 * HH + col];
        float v3 = h[(size_t)s3 * HH + col];
        a0 = fmaf(v0, w0, a0); a1 = fmaf(v1, w1, a1);
        a2 = fmaf(v2, w2, a2); a3 = fmaf(v3, w3, a3);
    }
    for (; e < e1; ++e) {
        int s = csrc[e];
        a0 = fmaf(h[(size_t)s * HH + col], dinv[s], a0);
    }
    float acc = (a0 + a1) + (a2 + a3);
    float r = tanh_fast(acc * dv + bias[col]);
    nf[(size_t)v * NF + col] = r;
    __nv_bfloat16 hi, lo;
    bf16_split(r, hi, lo);
    h1hi[(size_t)v * HH + col] = hi;
    h1lo[(size_t)v * HH + col] = lo;
}

__global__ void k_agg2(const float* __restrict__ h,
                       float* __restrict__ nf,
                       const int* __restrict__ rowptr, const int* __restrict__ csrc,
                       const float* __restrict__ dinv, const float* __restrict__ bias,
                       const float* __restrict__ W2, float* __restrict__ sv) {
    __shared__ float red[8];
    int v = blockIdx.x;
    int col = threadIdx.x;
    int lane = col & 31, wrp = col >> 5;
    float dv = dinv[v];
    int e0 = rowptr[v], e1 = rowptr[v + 1];
    float a0 = h[(size_t)v * HH + col] * dv, a1 = 0.f, a2 = 0.f, a3 = 0.f;
    int e = e0;
    for (; e + 4 <= e1; e += 4) {
        int s0 = csrc[e], s1 = csrc[e + 1], s2 = csrc[e + 2], s3 = csrc[e + 3];
        float w0 = dinv[s0], w1 = dinv[s1], w2 = dinv[s2], w3 = dinv[s3];
        float v0 = h[(size_t)s0 * HH + col];
        float v1 = h[(size_t)s1 * HH + col];
        float v2 = h[(size_t)s2 * HH + col];
        float v3 = h[(size_t)s3 * HH + col];
        a0 = fmaf(v0, w0, a0); a1 = fmaf(v1, w1, a1);
        a2 = fmaf(v2, w2, a2); a3 = fmaf(v3, w3, a3);
    }
    for (; e < e1; ++e) {
        int s = csrc[e];
        a0 = fmaf(h[(size_t)s * HH + col], dinv[s], a0);
    }
    float acc = (a0 + a1) + (a2 + a3);
    float r = tanh_fast(acc * dv + bias[col]);
    nf[(size_t)v * NF + HH + col] = r;
    float p = r * W2[col];
    #pragma unroll
    for (int off = 16; off; off >>= 1) p += __shfl_xor_sync(0xffffffffu, p, off);
    if (lane == 0) red[wrp] = p;
    __syncthreads();
    if (col == 0) {
        float t = 0.f;
        #pragma unroll
        for (int w = 0; w < 8; ++w) t += red[w];
        sv[v] = t;
    }
}

// ================= fused finale: agg_scalar + logits + edge scatter =================
__global__ void k_edge_final(float* __restrict__ nf, const float* __restrict__ sv,
                             const int* __restrict__ rp_d, const int* __restrict__ csrn,
                             const float* __restrict__ dinv, const float* __restrict__ b2,
                             const float* __restrict__ Wc, const float* __restrict__ bc,
                             float* __restrict__ logits,
                             const int* __restrict__ rp_src, const int* __restrict__ eid_src,
                             const int* __restrict__ eid_dst,
                             float* __restrict__ ep) {
    __shared__ float row[NF];
    __shared__ float part[8][CC];
    int v = blockIdx.x;
    int tid = threadIdx.x;
    int lane = tid & 31, wrp = tid >> 5;

    // load h1,h2 part of the row
    for (int j = tid; j < NF - 1; j += 256)
        row[j] = nf[(size_t)v * NF + j];
    // lane path: thread 0 computes the scalar-layer aggregation (col 512)
    if (tid == 0) {
        float dv = dinv[v];
        int e0 = rp_d[v], e1 = rp_d[v + 1];
        float a0 = sv[v] * dv, a1 = 0.f, a2 = 0.f, a3 = 0.f;
        int e = e0;
        for (; e + 4 <= e1; e += 4) {
            int s0 = csrn[e], s1 = csrn[e + 1], s2 = csrn[e + 2], s3 = csrn[e + 3];
            a0 = fmaf(sv[s0], dinv[s0], a0); a1 = fmaf(sv[s1], dinv[s1], a1);
            a2 = fmaf(sv[s2], dinv[s2], a2); a3 = fmaf(sv[s3], dinv[s3], a3);
        }
        for (; e < e1; ++e) {
            int sn = csrn[e];
            a0 = fmaf(sv[sn], dinv[sn], a0);
        }
        float r = tanh_fast(((a0 + a1) + (a2 + a3)) * dv + b2[0]);
        row[NF - 1] = r;
        nf[(size_t)v * NF + (NF - 1)] = r;
    }
    __syncthreads();

    // logits: dot(row, Wc[:,c]) + bc
    {
        float acc[CC] = {};
        for (int j = tid; j < NF; j += 256) {
            float x = row[j];
            const float* w = Wc + (size_t)j * CC;
            #pragma unroll
            for (int c = 0; c < CC; ++c) acc[c] = fmaf(x, w[c], acc[c]);
        }
        #pragma unroll
        for (int c = 0; c < CC; ++c)
            #pragma unroll
            for (int off = 16; off; off >>= 1) acc[c] += __shfl_xor_sync(0xffffffffu, acc[c], off);
        if (lane == 0) {
            #pragma unroll
            for (int c = 0; c < CC; ++c) part[wrp][c] = acc[c];
        }
        __syncthreads();
        if (tid < CC) {
            float t = bc[tid];
            #pragma unroll
            for (int w = 0; w < 8; ++w) t += part[w][tid];
            logits[(size_t)v * CC + tid] = t;
        }
    }

    // edge scatter (streaming stores)
    int s0 = rp_src[v], s1 = rp_src[v + 1];
    for (int e = s0; e < s1; ++e) {
        float* o = ep + (size_t)eid_src[e] * EPW;
        for (int j = tid; j < NF; j += 256)
            __stcs(o + j, row[j]);
    }
    int d0 = rp_d[v], d1 = rp_d[v + 1];
    for (int e = d0; e < d1; ++e) {
        float* o = ep + (size_t)eid_dst[e] * EPW + NF;
        for (int j = tid; j < NF; j += 256)
            __stcs(o + j, row[j]);
    }
}

// ================= launch =================
extern "C" void kernel_launch(void* const* d_in, const int* in_sizes, int n_in,
                              void* d_out, int out_size) {
    const float* x    = (const float*)d_in[0];
    const int*   ei   = (const int*)d_in[1];
    const float* W0   = (const float*)d_in[2];
    const float* b0   = (const float*)d_in[3];
    const float* W1   = (const float*)d_in[4];
    const float* b1   = (const float*)d_in[5];
    const float* W2   = (const float*)d_in[6];
    const float* b2   = (const float*)d_in[7];
    const float* Wc   = (const float*)d_in[8];
    const float* bc   = (const float*)d_in[9];

    const int n = in_sizes[0] / DD;
    const int e = in_sizes[1] / 2;
    const int* src = ei;
    const int* dst = ei + e;

    float* out = (float*)d_out;
    float* logits = out;
    float* nf     = out + (size_t)n * CC;
    float* ep     = nf + (size_t)n * NF;

    float *buf_h, *buf_s, *dinv;
    int *cnt_d, *cnt_s, *cur_d, *cur_s, *rp_d, *rp_s, *csrn, *eid_d, *eid_s;
    __nv_bfloat16 *xhi, *xlo, *h1hi, *h1lo, *bthi, *btlo;
    cudaGetSymbolAddress((void**)&buf_h, g_buf_h);
    cudaGetSymbolAddress((void**)&buf_s, g_buf_s);
    cudaGetSymbolAddress((void**)&dinv, g_dinv);
    cudaGetSymbolAddress((void**)&cnt_d, g_cnt_dst);
    cudaGetSymbolAddress((void**)&cnt_s, g_cnt_src);
    cudaGetSymbolAddress((void**)&cur_d, g_cur_dst);
    cudaGetSymbolAddress((void**)&cur_s, g_cur_src);
    cudaGetSymbolAddress((void**)&rp_d, g_rp_dst);
    cudaGetSymbolAddress((void**)&rp_s, g_rp_src);
    cudaGetSymbolAddress((void**)&csrn, g_csr_srcnode);
    cudaGetSymbolAddress((void**)&eid_d, g_csr_eid_dst);
    cudaGetSymbolAddress((void**)&eid_s, g_csr_eid_src);
    cudaGetSymbolAddress((void**)&xhi, g_xhi);
    cudaGetSymbolAddress((void**)&xlo, g_xlo);
    cudaGetSymbolAddress((void**)&h1hi, g_h1hi);
    cudaGetSymbolAddress((void**)&h1lo, g_h1lo);
    cudaGetSymbolAddress((void**)&bthi, g_bthi);
    cudaGetSymbolAddress((void**)&btlo, g_btlo);

    cudaFuncSetAttribute(k_gemm_bf16, cudaFuncAttributeMaxDynamicSharedMemorySize, GEMM_SMEM);

    const int TB = 256;
    dim3 gg((n + 127) / 128, TCN / 128);
    dim3 wb1(HH / 32, TCN / 32);
    dim3 wt(32, 8);

    // -- 10 launches; GEMM1 at index 3 for the ncu capture slot --
    k_prep<<<ZB + WB + XB, 256>>>(x, W0, cnt_d, cnt_s, cur_d, cur_s,
                                  xhi, xlo, bthi, btlo);                           // 0
    k_count2<<<(e + TB - 1) / TB, TB>>>(src, dst, cnt_s, cnt_d, e);                // 1
    k_scan2<<<2, 1024>>>(cnt_d, cnt_s, rp_d, rp_s, dinv, n);                       // 2
    k_gemm_bf16<<<gg, 256, GEMM_SMEM>>>(xhi, xlo, bthi, btlo, buf_h, n, DD);       // 3
    k_fill<<<(e + TB - 1) / TB, TB>>>(src, dst, rp_d, rp_s, cur_d, cur_s,
                                      csrn, eid_d, eid_s, e);                      // 4
    k_agg1<<<n, HH>>>(buf_h, nf, rp_d, csrn, dinv, b0, h1hi, h1lo);                // 5
    k_cvt_w<<<wb1, wt>>>(W1, bthi, btlo, HH);                                      // 6
    k_gemm_bf16<<<gg, 256, GEMM_SMEM>>>(h1hi, h1lo, bthi, btlo, buf_h, n, HH);     // 7
    k_agg2<<<n, HH>>>(buf_h, nf, rp_d, csrn, dinv, b1, W2, buf_s);                 // 8
    k_edge_final<<<n, 256>>>(nf, buf_s, rp_d, csrn, dinv, b2, Wc, bc, logits,
                             rp_s, eid_s, eid_d, ep);                              // 9
}

// round 17
// speedup vs baseline: 1.2079x; 1.0442x over previous
#include <cuda_runtime.h>
#include <cuda_bf16.h>
#include <math.h>
#include <stdint.h>

// Problem constants
#define NN 20000
#define EE 160000
#define DD 768
#define HH 256
#define CC 10
#define NF 513          // 2H+1
#define EPW 1026        // 2*(2H+1)
#define TCN 256         // GEMM N (fixed)

// -------- scratch (static device arrays are allowed) --------
__device__ float g_buf_h[NN * HH];
__device__ float g_buf_s[NN];
__device__ float g_dinv[NN];
__device__ int   g_cnt_dst[NN];
__device__ int   g_cnt_src[NN];
__device__ int   g_cur_dst[NN];
__device__ int   g_cur_src[NN];
__device__ int   g_rp_dst[NN + 1];
__device__ int   g_rp_src[NN + 1];
__device__ int   g_csr_srcnode[EE];
__device__ int   g_csr_eid_dst[EE];
__device__ int   g_csr_eid_src[EE];
__device__ __nv_bfloat16 g_xhi[NN * DD];
__device__ __nv_bfloat16 g_xlo[NN * DD];
__device__ __nv_bfloat16 g_h1hi[NN * HH];
__device__ __nv_bfloat16 g_h1lo[NN * HH];
__device__ __nv_bfloat16 g_bthi[HH * DD];    // W0^T split
__device__ __nv_bfloat16 g_btlo[HH * DD];
__device__ __nv_bfloat16 g_bt2hi[HH * HH];   // W1^T split (separate so cvt can run early)
__device__ __nv_bfloat16 g_bt2lo[HH * HH];

// ================= helpers =================
__device__ __forceinline__ uint32_t smem_u32(const void* p) {
    uint32_t a;
    asm("{ .reg .u64 t; cvta.to.shared.u64 t, %1; cvt.u32.u64 %0, t; }" : "=r"(a) : "l"(p));
    return a;
}
__device__ __forceinline__ void ldsm4(uint32_t* r, uint32_t addr) {
    asm volatile("ldmatrix.sync.aligned.m8n8.x4.shared.b16 {%0,%1,%2,%3}, [%4];"
                 : "=r"(r[0]), "=r"(r[1]), "=r"(r[2]), "=r"(r[3]) : "r"(addr));
}
__device__ __forceinline__ void mma_bf16(float* c, const uint32_t* a, const uint32_t* b) {
    asm volatile(
        "mma.sync.aligned.m16n8k16.row.col.f32.bf16.bf16.f32 "
        "{%0,%1,%2,%3}, {%4,%5,%6,%7}, {%8,%9}, {%0,%1,%2,%3};"
        : "+f"(c[0]), "+f"(c[1]), "+f"(c[2]), "+f"(c[3])
        : "r"(a[0]), "r"(a[1]), "r"(a[2]), "r"(a[3]), "r"(b[0]), "r"(b[1]));
}
__device__ __forceinline__ void cp16(uint32_t dst, const void* src, int sz) {
    asm volatile("cp.async.cg.shared.global [%0], [%1], 16, %2;"
                 :: "r"(dst), "l"(src), "r"(sz));
}
#define CP_COMMIT() asm volatile("cp.async.commit_group;" ::: "memory")
#define CP_WAIT(n)  asm volatile("cp.async.wait_group %0;" :: "n"(n) : "memory")

__device__ __forceinline__ float tanh_fast(float x) {
    float y; asm("tanh.approx.f32 %0, %1;" : "=f"(y) : "f"(x)); return y;
}
__device__ __forceinline__ void bf16_split(float v, __nv_bfloat16& hi, __nv_bfloat16& lo) {
    hi = __float2bfloat16(v);
    lo = __float2bfloat16(v - __bfloat162float(hi));
}

// ===== bf16 GEMM: BM=64, BN=128, BK=32, 128 thr (4 warps 1m x 4n), 2-stage, 3 blocks/SM ====
// C[M x 256] = A[M x K] * Bt[256 x K]^T   (A,Bt pre-split bf16 hi/lo, row-major)
#define BKK 32
#define SPAD 40                              // bf16 elems per smem row (80B, conflict-free)
#define MAT_A (64 * SPAD * 2)                // 5120
#define MAT_B (128 * SPAD * 2)               // 10240
#define STAGE_BYTES (2 * MAT_A + 2 * MAT_B)  // 30720
#define GEMM_SMEM (2 * STAGE_BYTES)          // 61440

__global__ void __launch_bounds__(128, 3) k_gemm_bf16(
    const __nv_bfloat16* __restrict__ Ahi, const __nv_bfloat16* __restrict__ Alo,
    const __nv_bfloat16* __restrict__ Bthi, const __nv_bfloat16* __restrict__ Btlo,
    float* __restrict__ C, int M, int K)
{
    extern __shared__ char smem[];
    const uint32_t sbase = smem_u32(smem);
    const int tid = threadIdx.x;
    const int wid = tid >> 5, lane = tid & 31;
    const int row0 = blockIdx.x * 64;
    const int col0 = blockIdx.y * 128;
    const int wn = wid;                      // 4 n-positions, warp tile 64x32

    const int a_row = (lane & 7) + ((lane >> 3) & 1) * 8;
    const int a_col = ((lane >> 4) & 1) * 8;
    const int b_row = (lane & 7) + ((lane >> 4) & 1) * 8;
    const int b_col = ((lane >> 3) & 1) * 8;

    float acc[4][4][4] = {};
    const int nchunks = K / BKK;

    auto load_stage = [&](int buf, int c) {
        const int k0 = c * BKK;
        const uint32_t sA_h = sbase + buf * STAGE_BYTES;
        const uint32_t sA_l = sA_h + MAT_A;
        const uint32_t sB_h = sA_l + MAT_A;
        const uint32_t sB_l = sB_h + MAT_B;
        #pragma unroll
        for (int t = tid; t < 256; t += 128) {          // A: 64 rows x 4 chunks of 16B
            int r = t >> 2, ch = t & 3;
            int gr = row0 + r;
            int ok = (gr < M);
            size_t off = (size_t)(ok ? gr : 0) * K + k0 + ch * 8;
            uint32_t d = (uint32_t)((r * SPAD + ch * 8) * 2);
            cp16(sA_h + d, Ahi + off, ok ? 16 : 0);
            cp16(sA_l + d, Alo + off, ok ? 16 : 0);
        }
        #pragma unroll
        for (int t = tid; t < 512; t += 128) {          // B: 128 n-rows x 4 chunks
            int n = t >> 2, ch = t & 3;
            size_t off = (size_t)(col0 + n) * K + k0 + ch * 8;
            uint32_t d = (uint32_t)((n * SPAD + ch * 8) * 2);
            cp16(sB_h + d, Bthi + off, 16);
            cp16(sB_l + d, Btlo + off, 16);
        }
    };

    auto compute_stage = [&](int buf) {
        const uint32_t sA_h = sbase + buf * STAGE_BYTES;
        const uint32_t sA_l = sA_h + MAT_A;
        const uint32_t sB_h = sA_l + MAT_A;
        const uint32_t sB_l = sB_h + MAT_B;
        #pragma unroll
        for (int ks = 0; ks < 2; ++ks) {
            const int kc = ks * 16;
            uint32_t ah[4][4], al[4][4], bh[4][2], bl[4][2];
            #pragma unroll
            for (int mf = 0; mf < 4; ++mf) {
                uint32_t off = (uint32_t)((mf * 16 + a_row) * SPAD + kc + a_col) * 2;
                ldsm4(ah[mf], sA_h + off);
            }
            #pragma unroll
            for (int np = 0; np < 2; ++np) {
                uint32_t off = (uint32_t)((wn * 32 + np * 16 + b_row) * SPAD + kc + b_col) * 2;
                uint32_t t[4];
                ldsm4(t, sB_h + off);
                bh[np * 2][0] = t[0]; bh[np * 2][1] = t[1];
                bh[np * 2 + 1][0] = t[2]; bh[np * 2 + 1][1] = t[3];
            }
            #pragma unroll
            for (int mf = 0; mf < 4; ++mf)
                #pragma unroll
                for (int nf = 0; nf < 4; ++nf)
                    mma_bf16(acc[mf][nf], ah[mf], bh[nf]);
            #pragma unroll
            for (int np = 0; np < 2; ++np) {
                uint32_t off = (uint32_t)((wn * 32 + np * 16 + b_row) * SPAD + kc + b_col) * 2;
                uint32_t t[4];
                ldsm4(t, sB_l + off);
                bl[np * 2][0] = t[0]; bl[np * 2][1] = t[1];
                bl[np * 2 + 1][0] = t[2]; bl[np * 2 + 1][1] = t[3];
            }
            #pragma unroll
            for (int mf = 0; mf < 4; ++mf)
                #pragma unroll
                for (int nf = 0; nf < 4; ++nf)
                    mma_bf16(acc[mf][nf], ah[mf], bl[nf]);
            #pragma unroll
            for (int mf = 0; mf < 4; ++mf) {
                uint32_t off = (uint32_t)((mf * 16 + a_row) * SPAD + kc + a_col) * 2;
                ldsm4(al[mf], sA_l + off);
            }
            #pragma unroll
            for (int mf = 0; mf < 4; ++mf)
                #pragma unroll
                for (int nf = 0; nf < 4; ++nf)
                    mma_bf16(acc[mf][nf], al[mf], bh[nf]);
        }
    };

    // 2-stage pipeline, one barrier per chunk
    load_stage(0, 0);
    CP_COMMIT();
    for (int c = 0; c < nchunks; ++c) {
        CP_WAIT(0);
        __syncthreads();
        if (c + 1 < nchunks) {
            load_stage((c + 1) & 1, c + 1);
            CP_COMMIT();
        }
        compute_stage(c & 1);
    }

    const int gq = lane >> 2, rq = lane & 3;
    #pragma unroll
    for (int mf = 0; mf < 4; ++mf) {
        int gr0 = row0 + mf * 16 + gq;
        int gr1 = gr0 + 8;
        #pragma unroll
        for (int nf = 0; nf < 4; ++nf) {
            int gc = col0 + wn * 32 + nf * 8 + rq * 2;
            if (gr0 < M) {
                C[(size_t)gr0 * TCN + gc]     = acc[mf][nf][0];
                C[(size_t)gr0 * TCN + gc + 1] = acc[mf][nf][1];
            }
            if (gr1 < M) {
                C[(size_t)gr1 * TCN + gc]     = acc[mf][nf][2];
                C[(size_t)gr1 * TCN + gc + 1] = acc[mf][nf][3];
            }
        }
    }
}

// ================= fused prep: zero counters + cvt W0 + cvt x =================
#define ZB 79                        // ceil(20000/256)
#define WB_K (DD / 32)               // 24
#define WB_N (TCN / 32)              // 8
#define WB (WB_K * WB_N)             // 192
#define XB (NN * DD / 4 / 256)       // 15000

__global__ void k_prep(const float* __restrict__ x, const float* __restrict__ W0,
                       int* cnt_d, int* cnt_s, int* cur_d, int* cur_s,
                       __nv_bfloat16* __restrict__ xhi, __nv_bfloat16* __restrict__ xlo,
                       __nv_bfloat16* __restrict__ bthi, __nv_bfloat16* __restrict__ btlo) {
    int b = blockIdx.x;
    if (b < ZB) {
        int i = b * 256 + threadIdx.x;
        if (i < NN) { cnt_d[i] = 0; cnt_s[i] = 0; cur_d[i] = 0; cur_s[i] = 0; }
        return;
    }
    b -= ZB;
    if (b < WB) {
        __shared__ float t[32][33];
        int kb = (b % WB_K) * 32, nb = (b / WB_K) * 32;
        int tx = threadIdx.x & 31, ty = threadIdx.x >> 5;
        #pragma unroll
        for (int j = ty; j < 32; j += 8)
            t[j][tx] = W0[(size_t)(kb + j) * TCN + nb + tx];
        __syncthreads();
        #pragma unroll
        for (int j = ty; j < 32; j += 8) {
            __nv_bfloat16 h, l;
            bf16_split(t[tx][j], h, l);
            bthi[(size_t)(nb + j) * DD + kb + tx] = h;
            btlo[(size_t)(nb + j) * DD + kb + tx] = l;
        }
        return;
    }
    b -= WB;
    int i = b * 256 + threadIdx.x;
    float4 v = reinterpret_cast<const float4*>(x)[i];
    __nv_bfloat16 h0, h1, h2, h3, l0, l1, l2, l3;
    bf16_split(v.x, h0, l0); bf16_split(v.y, h1, l1);
    bf16_split(v.z, h2, l2); bf16_split(v.w, h3, l3);
    reinterpret_cast<__nv_bfloat162*>(xhi)[i * 2]     = __nv_bfloat162(h0, h1);
    reinterpret_cast<__nv_bfloat162*>(xhi)[i * 2 + 1] = __nv_bfloat162(h2, h3);
    reinterpret_cast<__nv_bfloat162*>(xlo)[i * 2]     = __nv_bfloat162(l0, l1);
    reinterpret_cast<__nv_bfloat162*>(xlo)[i * 2 + 1] = __nv_bfloat162(l2, l3);
}

__global__ void k_cvt_w(const float* __restrict__ W,
                        __nv_bfloat16* __restrict__ bthi, __nv_bfloat16* __restrict__ btlo,
                        int K) {
    __shared__ float t[32][33];
    int kb = blockIdx.x * 32, nb = blockIdx.y * 32;
    int tx = threadIdx.x, ty = threadIdx.y;
    #pragma unroll
    for (int j = ty; j < 32; j += 8)
        t[j][tx] = W[(size_t)(kb + j) * TCN + nb + tx];
    __syncthreads();
    #pragma unroll
    for (int j = ty; j < 32; j += 8) {
        __nv_bfloat16 h, l;
        bf16_split(t[tx][j], h, l);
        bthi[(size_t)(nb + j) * K + kb + tx] = h;
        btlo[(size_t)(nb + j) * K + kb + tx] = l;
    }
}

// ================= CSR build =================
__global__ void k_count2(const int* __restrict__ src, const int* __restrict__ dst,
                         int* cnt_src, int* cnt_dst, int e) {
    int i = blockIdx.x * blockDim.x + threadIdx.x;
    if (i < e) {
        atomicAdd(&cnt_dst[dst[i]], 1);
        atomicAdd(&cnt_src[src[i]], 1);
    }
}

__global__ void k_scan2(const int* __restrict__ cnt_d, const int* __restrict__ cnt_s,
                        int* rp_d, int* rp_s, float* dinv, int n) {
    const int* cnt = (blockIdx.x == 0) ? cnt_d : cnt_s;
    int* rowptr    = (blockIdx.x == 0) ? rp_d : rp_s;
    __shared__ int wsum[32];
    __shared__ int s_carry;
    int lane = threadIdx.x & 31, wid = threadIdx.x >> 5;
    if (threadIdx.x == 0) { rowptr[0] = 0; s_carry = 0; }
    __syncthreads();
    for (int base = 0; base < n; base += 1024) {
        int i = base + threadIdx.x;
        int x = (i < n) ? cnt[i] : 0;
        #pragma unroll
        for (int off = 1; off < 32; off <<= 1) {
            int t = __shfl_up_sync(0xffffffffu, x, off);
            if (lane >= off) x += t;
        }
        if (lane == 31) wsum[wid] = x;
        __syncthreads();
        if (wid == 0) {
            int w = wsum[lane];
            #pragma unroll
            for (int off = 1; off < 32; off <<= 1) {
                int t = __shfl_up_sync(0xffffffffu, w, off);
                if (lane >= off) w += t;
            }
            wsum[lane] = w;
        }
        __syncthreads();
        int carry_now = s_carry;
        int excl_w = (wid > 0) ? wsum[wid - 1] : 0;
        if (i < n) rowptr[i + 1] = x + excl_w + carry_now;
        __syncthreads();
        if (threadIdx.x == 0) s_carry = carry_now + wsum[31];
        __syncthreads();
    }
    if (blockIdx.x == 0) {
        for (int i = threadIdx.x; i < n; i += 1024)
            dinv[i] = rsqrtf((float)(cnt_d[i] + 1));
    }
}

__global__ void k_fill(const int* __restrict__ src, const int* __restrict__ dst,
                       const int* __restrict__ rp_dst, const int* __restrict__ rp_src,
                       int* cur_dst, int* cur_src,
                       int* csr_srcnode, int* csr_eid_dst, int* csr_eid_src, int e) {
    int i = blockIdx.x * blockDim.x + threadIdx.x;
    if (i < e) {
        int s = src[i], d = dst[i];
        int pd = rp_dst[d] + atomicAdd(&cur_dst[d], 1);
        csr_srcnode[pd] = s;
        csr_eid_dst[pd] = i;
        int ps = rp_src[s] + atomicAdd(&cur_src[s], 1);
        csr_eid_src[ps] = i;
    }
}

// ================= aggregation (MLP=4) =================
__global__ void k_agg1(const float* __restrict__ h,
                       float* __restrict__ nf,
                       const int* __restrict__ rowptr, const int* __restrict__ csrc,
                       const float* __restrict__ dinv, const float* __restrict__ bias,
                       __nv_bfloat16* __restrict__ h1hi, __nv_bfloat16* __restrict__ h1lo) {
    int v = blockIdx.x;
    int col = threadIdx.x;
    float dv = dinv[v];
    int e0 = rowptr[v], e1 = rowptr[v + 1];
    float a0 = h[(size_t)v * HH + col] * dv, a1 = 0.f, a2 = 0.f, a3 = 0.f;
    int e = e0;
    for (; e + 4 <= e1; e += 4) {
        int s0 = csrc[e], s1 = csrc[e + 1], s2 = csrc[e + 2], s3 = csrc[e + 3];
        float w0 = dinv[s0], w1 = dinv[s1], w2 = dinv[s2], w3 = dinv[s3];
        float v0 = h[(size_t)s0 * HH + col];
        float v1 = h[(size_t)s1 * HH + col];
        float v2 = h[(size_t)s2 * HH + col];
        float v3 = h[(size_t)s3 * HH + col];
        a0 = fmaf(v0, w0, a0); a1 = fmaf(v1, w1, a1);
        a2 = fmaf(v2, w2, a2); a3 = fmaf(v3, w3, a3);
    }
    for (; e < e1; ++e) {
        int s = csrc[e];
        a0 = fmaf(h[(size_t)s * HH + col], dinv[s], a0);
    }
    float acc = (a0 + a1) + (a2 + a3);
    float r = tanh_fast(acc * dv + bias[col]);
    nf[(size_t)v * NF + col] = r;
    __nv_bfloat16 hi, lo;
    bf16_split(r, hi, lo);
    h1hi[(size_t)v * HH + col] = hi;
    h1lo[(size_t)v * HH + col] = lo;
}

__global__ void k_agg2(const float* __restrict__ h,
                       float* __restrict__ nf,
                       const int* __restrict__ rowptr, const int* __restrict__ csrc,
                       const float* __restrict__ dinv, const float* __restrict__ bias,
                       const float* __restrict__ W2, float* __restrict__ sv) {
    __shared__ float red[8];
    int v = blockIdx.x;
    int col = threadIdx.x;
    int lane = col & 31, wrp = col >> 5;
    float dv = dinv[v];
    int e0 = rowptr[v], e1 = rowptr[v + 1];
    float a0 = h[(size_t)v * HH + col] * dv, a1 = 0.f, a2 = 0.f, a3 = 0.f;
    int e = e0;
    for (; e + 4 <= e1; e += 4) {
        int s0 = csrc[e], s1 = csrc[e + 1], s2 = csrc[e + 2], s3 = csrc[e + 3];
        float w0 = dinv[s0], w1 = dinv[s1], w2 = dinv[s2], w3 = dinv[s3];
        float v0 = h[(size_t)s0 * HH + col];
        float v1 = h[(size_t)s1 * HH + col];
        float v2 = h[(size_t)s2 * HH + col];
        float v3 = h[(size_t)s3 * HH + col];
        a0 = fmaf(v0, w0, a0); a1 = fmaf(v1, w1, a1);
        a2 = fmaf(v2, w2, a2); a3 = fmaf(v3, w3, a3);
    }
    for (; e < e1; ++e) {
        int s = csrc[e];
        a0 = fmaf(h[(size_t)s * HH + col], dinv[s], a0);
    }
    float acc = (a0 + a1) + (a2 + a3);
    float r = tanh_fast(acc * dv + bias[col]);
    nf[(size_t)v * NF + HH + col] = r;
    float p = r * W2[col];
    #pragma unroll
    for (int off = 16; off; off >>= 1) p += __shfl_xor_sync(0xffffffffu, p, off);
    if (lane == 0) red[wrp] = p;
    __syncthreads();
    if (col == 0) {
        float t = 0.f;
        #pragma unroll
        for (int w = 0; w < 8; ++w) t += red[w];
        sv[v] = t;
    }
}

// ================= fused finale: agg_scalar + logits + edge scatter =================
__global__ void k_edge_final(float* __restrict__ nf, const float* __restrict__ sv,
                             const int* __restrict__ rp_d, const int* __restrict__ csrn,
                             const float* __restrict__ dinv, const float* __restrict__ b2,
                             const float* __restrict__ Wc, const float* __restrict__ bc,
                             float* __restrict__ logits,
                             const int* __restrict__ rp_src, const int* __restrict__ eid_src,
                             const int* __restrict__ eid_dst,
                             float* __restrict__ ep) {
    __shared__ float row[NF];
    __shared__ float part[8][CC];
    int v = blockIdx.x;
    int tid = threadIdx.x;
    int lane = tid & 31, wrp = tid >> 5;

    for (int j = tid; j < NF - 1; j += 256)
        row[j] = nf[(size_t)v * NF + j];
    if (tid == 0) {
        float dv = dinv[v];
        int e0 = rp_d[v], e1 = rp_d[v + 1];
        float a0 = sv[v] * dv, a1 = 0.f, a2 = 0.f, a3 = 0.f;
        int e = e0;
        for (; e + 4 <= e1; e += 4) {
            int s0 = csrn[e], s1 = csrn[e + 1], s2 = csrn[e + 2], s3 = csrn[e + 3];
            a0 = fmaf(sv[s0], dinv[s0], a0); a1 = fmaf(sv[s1], dinv[s1], a1);
            a2 = fmaf(sv[s2], dinv[s2], a2); a3 = fmaf(sv[s3], dinv[s3], a3);
        }
        for (; e < e1; ++e) {
            int sn = csrn[e];
            a0 = fmaf(sv[sn], dinv[sn], a0);
        }
        float r = tanh_fast(((a0 + a1) + (a2 + a3)) * dv + b2[0]);
        row[NF - 1] = r;
        nf[(size_t)v * NF + (NF - 1)] = r;
    }
    __syncthreads();

    {
        float acc[CC] = {};
        for (int j = tid; j < NF; j += 256) {
            float x = row[j];
            const float* w = Wc + (size_t)j * CC;
            #pragma unroll
            for (int c = 0; c < CC; ++c) acc[c] = fmaf(x, w[c], acc[c]);
        }
        #pragma unroll
        for (int c = 0; c < CC; ++c)
            #pragma unroll
            for (int off = 16; off; off >>= 1) acc[c] += __shfl_xor_sync(0xffffffffu, acc[c], off);
        if (lane == 0) {
            #pragma unroll
            for (int c = 0; c < CC; ++c) part[wrp][c] = acc[c];
        }
        __syncthreads();
        if (tid < CC) {
            float t = bc[tid];
            #pragma unroll
            for (int w = 0; w < 8; ++w) t += part[w][tid];
            logits[(size_t)v * CC + tid] = t;
        }
    }

    int s0 = rp_src[v], s1 = rp_src[v + 1];
    for (int e = s0; e < s1; ++e) {
        float* o = ep + (size_t)eid_src[e] * EPW;
        for (int j = tid; j < NF; j += 256)
            __stcs(o + j, row[j]);
    }
    int d0 = rp_d[v], d1 = rp_d[v + 1];
    for (int e = d0; e < d1; ++e) {
        float* o = ep + (size_t)eid_dst[e] * EPW + NF;
        for (int j = tid; j < NF; j += 256)
            __stcs(o + j, row[j]);
    }
}

// ================= launch =================
extern "C" void kernel_launch(void* const* d_in, const int* in_sizes, int n_in,
                              void* d_out, int out_size) {
    const float* x    = (const float*)d_in[0];
    const int*   ei   = (const int*)d_in[1];
    const float* W0   = (const float*)d_in[2];
    const float* b0   = (const float*)d_in[3];
    const float* W1   = (const float*)d_in[4];
    const float* b1   = (const float*)d_in[5];
    const float* W2   = (const float*)d_in[6];
    const float* b2   = (const float*)d_in[7];
    const float* Wc   = (const float*)d_in[8];
    const float* bc   = (const float*)d_in[9];

    const int n = in_sizes[0] / DD;
    const int e = in_sizes[1] / 2;
    const int* src = ei;
    const int* dst = ei + e;

    float* out = (float*)d_out;
    float* logits = out;
    float* nf     = out + (size_t)n * CC;
    float* ep     = nf + (size_t)n * NF;

    float *buf_h, *buf_s, *dinv;
    int *cnt_d, *cnt_s, *cur_d, *cur_s, *rp_d, *rp_s, *csrn, *eid_d, *eid_s;
    __nv_bfloat16 *xhi, *xlo, *h1hi, *h1lo, *bthi, *btlo, *bt2hi, *bt2lo;
    cudaGetSymbolAddress((void**)&buf_h, g_buf_h);
    cudaGetSymbolAddress((void**)&buf_s, g_buf_s);
    cudaGetSymbolAddress((void**)&dinv, g_dinv);
    cudaGetSymbolAddress((void**)&cnt_d, g_cnt_dst);
    cudaGetSymbolAddress((void**)&cnt_s, g_cnt_src);
    cudaGetSymbolAddress((void**)&cur_d, g_cur_dst);
    cudaGetSymbolAddress((void**)&cur_s, g_cur_src);
    cudaGetSymbolAddress((void**)&rp_d, g_rp_dst);
    cudaGetSymbolAddress((void**)&rp_s, g_rp_src);
    cudaGetSymbolAddress((void**)&csrn, g_csr_srcnode);
    cudaGetSymbolAddress((void**)&eid_d, g_csr_eid_dst);
    cudaGetSymbolAddress((void**)&eid_s, g_csr_eid_src);
    cudaGetSymbolAddress((void**)&xhi, g_xhi);
    cudaGetSymbolAddress((void**)&xlo, g_xlo);
    cudaGetSymbolAddress((void**)&h1hi, g_h1hi);
    cudaGetSymbolAddress((void**)&h1lo, g_h1lo);
    cudaGetSymbolAddress((void**)&bthi, g_bthi);
    cudaGetSymbolAddress((void**)&btlo, g_btlo);
    cudaGetSymbolAddress((void**)&bt2hi, g_bt2hi);
    cudaGetSymbolAddress((void**)&bt2lo, g_bt2lo);

    cudaFuncSetAttribute(k_gemm_bf16, cudaFuncAttributeMaxDynamicSharedMemorySize, GEMM_SMEM);

    const int TB = 256;
    dim3 gg((n + 63) / 64, TCN / 128);    // 313 x 2 = 626 blocks
    dim3 wb1(HH / 32, TCN / 32);
    dim3 wt(32, 8);

    // -- 10 launches; GEMM1 at index 3 for the ncu capture slot --
    k_prep<<<ZB + WB + XB, 256>>>(x, W0, cnt_d, cnt_s, cur_d, cur_s,
                                  xhi, xlo, bthi, btlo);                           // 0
    k_count2<<<(e + TB - 1) / TB, TB>>>(src, dst, cnt_s, cnt_d, e);                // 1
    k_cvt_w<<<wb1, wt>>>(W1, bt2hi, bt2lo, HH);                                    // 2
    k_gemm_bf16<<<gg, 128, GEMM_SMEM>>>(xhi, xlo, bthi, btlo, buf_h, n, DD);       // 3
    k_scan2<<<2, 1024>>>(cnt_d, cnt_s, rp_d, rp_s, dinv, n);                       // 4
    k_fill<<<(e + TB - 1) / TB, TB>>>(src, dst, rp_d, rp_s, cur_d, cur_s,
                                      csrn, eid_d, eid_s, e);                      // 5
    k_agg1<<<n, HH>>>(buf_h, nf, rp_d, csrn, dinv, b0, h1hi, h1lo);                // 6
    k_gemm_bf16<<<gg, 128, GEMM_SMEM>>>(h1hi, h1lo, bt2hi, bt2lo, buf_h, n, HH);   // 7
    k_agg2<<<n, HH>>>(buf_h, nf, rp_d, csrn, dinv, b1, W2, buf_s);                 // 8
    k_edge_final<<<n, 256>>>(nf, buf_s, rp_d, csrn, dinv, b2, Wc, bc, logits,
                             rp_s, eid_s, eid_d, ep);                              // 9
}